// round 2
// baseline (speedup 1.0000x reference)
#include <cuda_runtime.h>
#include <cstdint>
#include <math.h>

#define NEGV 1000000000000.0f

// ---------------- scratch (static device globals; no allocs) ----------------
__device__ float g_cos[1024 * 32];
__device__ float g_sin[1024 * 32];
__device__ float g_q[4 * 1024 * 64];     // rope'd q, pre-scaled by 1/8
__device__ float g_k[4 * 1024 * 64];     // rope'd k
__device__ float g_bA[4 * 16 * 1024];    // bias[b, n, 2o]/2   -> indexed [b][o][n]
__device__ float g_bB[4 * 16 * 1024];    // bias[b, m, 2o+1]/2 -> indexed [b][o][m]

// ---------------- packed f32x2 helpers ----------------
__device__ __forceinline__ unsigned long long pk2(float lo, float hi) {
    unsigned long long r;
    asm("mov.b64 %0, {%1,%2};" : "=l"(r) : "f"(lo), "f"(hi));
    return r;
}
__device__ __forceinline__ void fma2(unsigned long long& d, unsigned long long a,
                                     unsigned long long b) {
    asm("fma.rn.f32x2 %0, %1, %2, %0;" : "+l"(d) : "l"(a), "l"(b));
}
__device__ __forceinline__ float2 up2(unsigned long long v) {
    float2 r;
    asm("mov.b64 {%0,%1}, %2;" : "=f"(r.x), "=f"(r.y) : "l"(v));
    return r;
}

// ---------------- kernel 0: sinusoidal tables ----------------
__global__ void pos_kernel() {
    int idx = blockIdx.x * blockDim.x + threadIdx.x;  // 32768 = 1024*32
    int s = idx >> 5, j = idx & 31;
    // inv_freq = 10000^(-j/32), computed accurately then rounded to fp32,
    // angle multiply done in fp32 to mimic the reference rounding.
    double invf = exp(-(double)j * (9.210340371976184 / 32.0));
    float ang = (float)s * (float)invf;
    float sv, cv;
    sincosf(ang, &sv, &cv);
    g_sin[idx] = sv;
    g_cos[idx] = cv;
}

// ---------------- kernel 1: h = x@W1+b1, RoPE -> q/k, bias -> bA/bB ----------
// Grid: 128 blocks (32 rows each), 256 threads.
// GEMM tile: BM=32, BN=128(full), BK=64, micro-tile 4m x 4n per thread.
__global__ __launch_bounds__(256) void k1_kernel(
    const float* __restrict__ x, const float* __restrict__ W1,
    const float* __restrict__ b1, const float* __restrict__ W2,
    const float* __restrict__ b2) {
    __shared__ __align__(16) float a_s[64][36];   // [k][m], padded rows (16B mult)
    __shared__ __align__(16) float b_s[64 * 128]; // [k][n]; reused as h_s later

    const int tid = threadIdx.x;
    const int tn = tid & 31;   // 4 n-cols: 4*tn .. 4*tn+3
    const int tm = tid >> 5;   // 4 m-rows: 4*tm .. 4*tm+3
    const int row0 = blockIdx.x * 32;

    // A staging map: one row per lane (conflict-free STS), warp owns 8 k's
    const int ar = tid & 31;
    const int akc = (tid >> 5) * 8;

    // acc packed in n: acc2[mi][0] = cols (4tn,4tn+1), [1] = (4tn+2,4tn+3)
    unsigned long long acc2[4][2];
    {
        float4 bv = *(const float4*)(b1 + 4 * tn);
        unsigned long long p0 = pk2(bv.x, bv.y), p1 = pk2(bv.z, bv.w);
#pragma unroll
        for (int mi = 0; mi < 4; mi++) { acc2[mi][0] = p0; acc2[mi][1] = p1; }
    }

    float4 pa0, pa1, pb[8];
    // prefetch tile 0
    {
        const float* xp = x + (size_t)(row0 + ar) * 768 + akc;
        pa0 = *(const float4*)xp;
        pa1 = *(const float4*)(xp + 4);
#pragma unroll
        for (int i = 0; i < 8; i++) {
            int lin = tid * 4 + 1024 * i;
            int kk = lin >> 7, col = lin & 127;
            pb[i] = *(const float4*)(W1 + (size_t)kk * 128 + col);
        }
    }

    for (int kt = 0; kt < 12; kt++) {
        __syncthreads();
        // stage smem from regs
        a_s[akc + 0][ar] = pa0.x; a_s[akc + 1][ar] = pa0.y;
        a_s[akc + 2][ar] = pa0.z; a_s[akc + 3][ar] = pa0.w;
        a_s[akc + 4][ar] = pa1.x; a_s[akc + 5][ar] = pa1.y;
        a_s[akc + 6][ar] = pa1.z; a_s[akc + 7][ar] = pa1.w;
#pragma unroll
        for (int i = 0; i < 8; i++) {
            int lin = tid * 4 + 1024 * i;
            int kk = lin >> 7, col = lin & 127;
            *(float4*)&b_s[kk * 128 + col] = pb[i];
        }
        __syncthreads();

        // prefetch next tile (overlaps with compute below)
        if (kt < 11) {
            int k0n = (kt + 1) * 64;
            const float* xp = x + (size_t)(row0 + ar) * 768 + k0n + akc;
            pa0 = *(const float4*)xp;
            pa1 = *(const float4*)(xp + 4);
#pragma unroll
            for (int i = 0; i < 8; i++) {
                int lin = tid * 4 + 1024 * i;
                int kk = lin >> 7, col = lin & 127;
                pb[i] = *(const float4*)(W1 + (size_t)(k0n + kk) * 128 + col);
            }
        }

#pragma unroll 16
        for (int kk = 0; kk < 64; kk++) {
            float4 av = *(const float4*)&a_s[kk][4 * tm];  // broadcast in warp
            ulonglong2 bv = *(const ulonglong2*)&b_s[kk * 128 + 4 * tn];
            unsigned long long am;
            am = pk2(av.x, av.x); fma2(acc2[0][0], am, bv.x); fma2(acc2[0][1], am, bv.y);
            am = pk2(av.y, av.y); fma2(acc2[1][0], am, bv.x); fma2(acc2[1][1], am, bv.y);
            am = pk2(av.z, av.z); fma2(acc2[2][0], am, bv.x); fma2(acc2[2][1], am, bv.y);
            am = pk2(av.w, av.w); fma2(acc2[3][0], am, bv.x); fma2(acc2[3][1], am, bv.y);
        }
    }

    // ---- epilogue: RoPE + store q/k, stash h into smem, then bias GEMM ----
    __syncthreads();                 // everyone done reading b_s
    float* h_s = b_s;                // reuse as h tile [32][stride 133]

    const int ie = (2 * tn) & 31;        // angle index for even element
    const int io = (2 * tn + 1) & 31;    // angle index for odd element
#pragma unroll
    for (int mi = 0; mi < 4; mi++) {
        float2 v0 = up2(acc2[mi][0]);    // h[4tn], h[4tn+1]
        float2 v1 = up2(acc2[mi][1]);    // h[4tn+2], h[4tn+3]
        int r = 4 * tm + mi;
        int rg = row0 + r;               // global row (b*1024 + s)
        int s = rg & 1023;

        // stash h for bias GEMM
        h_s[r * 133 + 4 * tn + 0] = v0.x;
        h_s[r * 133 + 4 * tn + 1] = v0.y;
        h_s[r * 133 + 4 * tn + 2] = v1.x;
        h_s[r * 133 + 4 * tn + 3] = v1.y;

        // RoPE: q[2tn]=h[4tn], q[2tn+1]=h[4tn+2]; k from odd h cols
        float ce = g_cos[s * 32 + ie], se = g_sin[s * 32 + ie];
        float co = g_cos[s * 32 + io], so = g_sin[s * 32 + io];
        float qe = v0.x, ke = v0.y, qo = v1.x, ko = v1.y;
        float2 qr, kr;
        qr.x = (qe * ce - qo * se) * 0.125f;   // fold 1/sqrt(64) into q
        qr.y = (qo * co + qe * so) * 0.125f;
        kr.x = ke * ce - ko * se;
        kr.y = ko * co + ke * so;
        *(float2*)&g_q[(size_t)rg * 64 + 2 * tn] = qr;
        *(float2*)&g_k[(size_t)rg * 64 + 2 * tn] = kr;
    }
    __syncthreads();                 // h_s fully written

    // bias: each thread -> row r, 4 consecutive out channels hb4..hb4+3
    {
        const int r = tid & 31;
        const int hb4 = (tid >> 5) * 4;
        float4 accb = *(const float4*)(b2 + hb4);
        const float* hp = h_s + r * 133;
#pragma unroll 8
        for (int kk = 0; kk < 128; kk++) {
            float hv = hp[kk];
            float4 wv = *(const float4*)(W2 + kk * 32 + hb4);  // uniform per warp
            accb.x += hv * wv.x;
            accb.y += hv * wv.y;
            accb.z += hv * wv.z;
            accb.w += hv * wv.w;
        }
        int b = row0 >> 10;
        int s = (row0 & 1023) + r;
        float vals[4] = {accb.x * 0.5f, accb.y * 0.5f, accb.z * 0.5f, accb.w * 0.5f};
#pragma unroll
        for (int j = 0; j < 4; j++) {
            int ho = hb4 + j;
            int o = ho >> 1;
            if (ho & 1) g_bB[(size_t)(b * 16 + o) * 1024 + s] = vals[j];
            else        g_bA[(size_t)(b * 16 + o) * 1024 + s] = vals[j];
        }
    }
}

// ---------------- kernel 2: logits ----------------
// Grid: (8 n-tiles, 32 m-tiles, 4 batch), 256 threads.
// Tile: 32m x 128n; dot(q',k') computed once, reused across 16 heads.
__global__ __launch_bounds__(256) void k2_kernel(const float* __restrict__ mask,
                                                 float* __restrict__ out) {
    __shared__ __align__(16) float q_s[64][36];    // [k][m]
    __shared__ __align__(16) float k_s[64 * 128];  // [k][n]

    const int tid = threadIdx.x;
    const int tn = tid & 31;
    const int tm = tid >> 5;
    const int b = blockIdx.z;
    const int m0 = blockIdx.y * 32;
    const int n0 = blockIdx.x * 128;

    // stage q tile (32 rows x 64)
    {
        int r = tid & 31, kc = (tid >> 5) * 8;
        const float* qp = g_q + (size_t)(b * 1024 + m0 + r) * 64 + kc;
        float4 a0 = *(const float4*)qp;
        float4 a1 = *(const float4*)(qp + 4);
        q_s[kc + 0][r] = a0.x; q_s[kc + 1][r] = a0.y;
        q_s[kc + 2][r] = a0.z; q_s[kc + 3][r] = a0.w;
        q_s[kc + 4][r] = a1.x; q_s[kc + 5][r] = a1.y;
        q_s[kc + 6][r] = a1.z; q_s[kc + 7][r] = a1.w;
    }
    // stage k tile (128 rows x 64), transposed into [k][n]
    {
        int r = tid >> 1, kc = (tid & 1) * 32;
        const float* kp = g_k + (size_t)(b * 1024 + n0 + r) * 64 + kc;
#pragma unroll
        for (int i = 0; i < 8; i++) {
            float4 v = *(const float4*)(kp + 4 * i);
            int kk = kc + 4 * i;
            k_s[(kk + 0) * 128 + r] = v.x;
            k_s[(kk + 1) * 128 + r] = v.y;
            k_s[(kk + 2) * 128 + r] = v.z;
            k_s[(kk + 3) * 128 + r] = v.w;
        }
    }
    __syncthreads();

    unsigned long long acc2[4][2];
#pragma unroll
    for (int mi = 0; mi < 4; mi++) { acc2[mi][0] = 0ULL; acc2[mi][1] = 0ULL; }

#pragma unroll 16
    for (int kk = 0; kk < 64; kk++) {
        float4 av = *(const float4*)&q_s[kk][4 * tm];  // broadcast
        ulonglong2 bv = *(const ulonglong2*)&k_s[kk * 128 + 4 * tn];
        unsigned long long am;
        am = pk2(av.x, av.x); fma2(acc2[0][0], am, bv.x); fma2(acc2[0][1], am, bv.y);
        am = pk2(av.y, av.y); fma2(acc2[1][0], am, bv.x); fma2(acc2[1][1], am, bv.y);
        am = pk2(av.z, av.z); fma2(acc2[2][0], am, bv.x); fma2(acc2[2][1], am, bv.y);
        am = pk2(av.w, av.w); fma2(acc2[3][0], am, bv.x); fma2(acc2[3][1], am, bv.y);
    }

    // unpack dots
    float d0[4][4];
#pragma unroll
    for (int mi = 0; mi < 4; mi++) {
        float2 u0 = up2(acc2[mi][0]);
        float2 u1 = up2(acc2[mi][1]);
        d0[mi][0] = u0.x; d0[mi][1] = u0.y; d0[mi][2] = u1.x; d0[mi][3] = u1.y;
    }

    const int nbase = n0 + 4 * tn;
    const int mbase = m0 + 4 * tm;

    // mask terms (per n-col)
    float pm[4], pen[4];
    {
        float4 mv = *(const float4*)(mask + b * 1024 + nbase);
        pm[0] = mv.x; pm[1] = mv.y; pm[2] = mv.z; pm[3] = mv.w;
#pragma unroll
        for (int j = 0; j < 4; j++) pen[j] = (1.0f - pm[j]) * NEGV;
    }

    for (int o = 0; o < 16; o++) {
        size_t hb = (size_t)(b * 16 + o) * 1024;
        float4 ba = *(const float4*)(g_bA + hb + nbase);   // per-n bias
        float4 bb = *(const float4*)(g_bB + hb + mbase);   // per-m bias
        float bav[4] = {ba.x, ba.y, ba.z, ba.w};
        float bbv[4] = {bb.x, bb.y, bb.z, bb.w};
        float* op = out + (hb + mbase) * 1024 + nbase;
#pragma unroll
        for (int mi = 0; mi < 4; mi++) {
            int mg = mbase + mi;
            float4 r;
            float v;
            v = d0[mi][0] + bav[0] + bbv[mi];
            v = v * pm[0] - pen[0];
            if (mg > nbase + 0) v -= NEGV;
            r.x = v;
            v = d0[mi][1] + bav[1] + bbv[mi];
            v = v * pm[1] - pen[1];
            if (mg > nbase + 1) v -= NEGV;
            r.y = v;
            v = d0[mi][2] + bav[2] + bbv[mi];
            v = v * pm[2] - pen[2];
            if (mg > nbase + 2) v -= NEGV;
            r.z = v;
            v = d0[mi][3] + bav[3] + bbv[mi];
            v = v * pm[3] - pen[3];
            if (mg > nbase + 3) v -= NEGV;
            r.w = v;
            *(float4*)(op + (size_t)mi * 1024) = r;
        }
    }
}

extern "C" void kernel_launch(void* const* d_in, const int* in_sizes, int n_in,
                              void* d_out, int out_size) {
    const float* x    = (const float*)d_in[0];  // (4,1024,768)
    const float* mask = (const float*)d_in[1];  // (4,1024)
    const float* W1   = (const float*)d_in[2];  // (768,128)
    const float* b1   = (const float*)d_in[3];  // (128)
    const float* W2   = (const float*)d_in[4];  // (128,32)
    const float* b2   = (const float*)d_in[5];  // (32)
    float* out = (float*)d_out;                 // (4,16,1024,1024)

    pos_kernel<<<128, 256>>>();
    k1_kernel<<<128, 256>>>(x, W1, b1, W2, b2);
    k2_kernel<<<dim3(8, 32, 4), 256>>>(mask, out);
}

// round 3
// speedup vs baseline: 1.1606x; 1.1606x over previous
#include <cuda_runtime.h>
#include <cstdint>
#include <math.h>

#define NEGV 1000000000000.0f

// ---------------- scratch (static device globals; no allocs) ----------------
__device__ float g_qT[4 * 64 * 1024];    // rope'd q, TRANSPOSED [b][d][m], pre-scaled 1/8
__device__ float g_kT[4 * 64 * 1024];    // rope'd k, TRANSPOSED [b][d][n]
__device__ float g_bA[4 * 16 * 1024];    // bias[b, n, 2o]/2   -> indexed [b][o][n]
__device__ float g_bB[4 * 16 * 1024];    // bias[b, m, 2o+1]/2 -> indexed [b][o][m]

// ---------------- packed f32x2 helpers ----------------
__device__ __forceinline__ unsigned long long pk2(float lo, float hi) {
    unsigned long long r;
    asm("mov.b64 %0, {%1,%2};" : "=l"(r) : "f"(lo), "f"(hi));
    return r;
}
__device__ __forceinline__ void fma2(unsigned long long& d, unsigned long long a,
                                     unsigned long long b) {
    asm("fma.rn.f32x2 %0, %1, %2, %0;" : "+l"(d) : "l"(a), "l"(b));
}
__device__ __forceinline__ unsigned long long fma2n(unsigned long long a,
                                                    unsigned long long b,
                                                    unsigned long long c) {
    unsigned long long d;
    asm("fma.rn.f32x2 %0, %1, %2, %3;" : "=l"(d) : "l"(a), "l"(b), "l"(c));
    return d;
}
__device__ __forceinline__ unsigned long long add2(unsigned long long a,
                                                   unsigned long long b) {
    unsigned long long d;
    asm("add.rn.f32x2 %0, %1, %2;" : "=l"(d) : "l"(a), "l"(b));
    return d;
}
__device__ __forceinline__ float2 up2(unsigned long long v) {
    float2 r;
    asm("mov.b64 {%0,%1}, %2;" : "=f"(r.x), "=f"(r.y) : "l"(v));
    return r;
}

// ---------------- kernel 1: h = x@W1+b1, RoPE -> qT/kT, bias -> bA/bB --------
// Grid: 128 blocks (32 rows each), 256 threads.
// GEMM tile: BM=32, BN=128(full), BK=64, micro-tile 4m x 4n per thread.
__global__ __launch_bounds__(256) void k1_kernel(
    const float* __restrict__ x, const float* __restrict__ W1,
    const float* __restrict__ b1, const float* __restrict__ W2,
    const float* __restrict__ b2) {
    __shared__ __align__(16) float a_s[64][36];   // [k][m], padded rows
    __shared__ __align__(16) float b_s[64 * 128]; // [k][n]; reused as h_s later
    __shared__ float invf_s[32];

    const int tid = threadIdx.x;
    const int tn = tid & 31;   // 4 n-cols: 4*tn .. 4*tn+3
    const int tm = tid >> 5;   // 4 m-rows: 4*tm .. 4*tm+3
    const int row0 = blockIdx.x * 32;

    if (tid < 32) {
        // inv_freq = 10000^(-tid/32), computed in double, rounded to fp32
        invf_s[tid] = (float)exp(-(double)tid * (9.210340371976184 / 32.0));
    }

    // A staging map: one row per lane (conflict-free STS), warp owns 8 k's
    const int ar = tid & 31;
    const int akc = (tid >> 5) * 8;

    // acc packed in n: acc2[mi][0] = cols (4tn,4tn+1), [1] = (4tn+2,4tn+3)
    unsigned long long acc2[4][2];
    {
        float4 bv = *(const float4*)(b1 + 4 * tn);
        unsigned long long p0 = pk2(bv.x, bv.y), p1 = pk2(bv.z, bv.w);
#pragma unroll
        for (int mi = 0; mi < 4; mi++) { acc2[mi][0] = p0; acc2[mi][1] = p1; }
    }

    float4 pa0, pa1, pb[8];
    // prefetch tile 0
    {
        const float* xp = x + (size_t)(row0 + ar) * 768 + akc;
        pa0 = *(const float4*)xp;
        pa1 = *(const float4*)(xp + 4);
#pragma unroll
        for (int i = 0; i < 8; i++) {
            int lin = tid * 4 + 1024 * i;
            int kk = lin >> 7, col = lin & 127;
            pb[i] = *(const float4*)(W1 + (size_t)kk * 128 + col);
        }
    }

    for (int kt = 0; kt < 12; kt++) {
        __syncthreads();
        // stage smem from regs
        a_s[akc + 0][ar] = pa0.x; a_s[akc + 1][ar] = pa0.y;
        a_s[akc + 2][ar] = pa0.z; a_s[akc + 3][ar] = pa0.w;
        a_s[akc + 4][ar] = pa1.x; a_s[akc + 5][ar] = pa1.y;
        a_s[akc + 6][ar] = pa1.z; a_s[akc + 7][ar] = pa1.w;
#pragma unroll
        for (int i = 0; i < 8; i++) {
            int lin = tid * 4 + 1024 * i;
            int kk = lin >> 7, col = lin & 127;
            *(float4*)&b_s[kk * 128 + col] = pb[i];
        }
        __syncthreads();

        // prefetch next tile (overlaps with compute below)
        if (kt < 11) {
            int k0n = (kt + 1) * 64;
            const float* xp = x + (size_t)(row0 + ar) * 768 + k0n + akc;
            pa0 = *(const float4*)xp;
            pa1 = *(const float4*)(xp + 4);
#pragma unroll
            for (int i = 0; i < 8; i++) {
                int lin = tid * 4 + 1024 * i;
                int kk = lin >> 7, col = lin & 127;
                pb[i] = *(const float4*)(W1 + (size_t)(k0n + kk) * 128 + col);
            }
        }

#pragma unroll 16
        for (int kk = 0; kk < 64; kk++) {
            float4 av = *(const float4*)&a_s[kk][4 * tm];  // broadcast in warp
            ulonglong2 bv = *(const ulonglong2*)&b_s[kk * 128 + 4 * tn];
            unsigned long long am;
            am = pk2(av.x, av.x); fma2(acc2[0][0], am, bv.x); fma2(acc2[0][1], am, bv.y);
            am = pk2(av.y, av.y); fma2(acc2[1][0], am, bv.x); fma2(acc2[1][1], am, bv.y);
            am = pk2(av.z, av.z); fma2(acc2[2][0], am, bv.x); fma2(acc2[2][1], am, bv.y);
            am = pk2(av.w, av.w); fma2(acc2[3][0], am, bv.x); fma2(acc2[3][1], am, bv.y);
        }
    }

    // ---- epilogue: RoPE + store qT/kT, stash h into smem, then bias GEMM ----
    __syncthreads();                 // everyone done reading b_s
    float* h_s = b_s;                // reuse as h tile [32][stride 133]

    const int b = row0 >> 10;
    const int ie = (2 * tn) & 31;        // angle index for even element
    const int io = (2 * tn + 1) & 31;    // angle index for odd element
    const float invfe = invf_s[ie];
    const float invfo = invf_s[io];
    float* qTe = g_qT + (size_t)(b * 64 + 2 * tn) * 1024;
    float* qTo = qTe + 1024;
    float* kTe = g_kT + (size_t)(b * 64 + 2 * tn) * 1024;
    float* kTo = kTe + 1024;

#pragma unroll
    for (int mi = 0; mi < 4; mi++) {
        float2 v0 = up2(acc2[mi][0]);    // h[4tn], h[4tn+1]
        float2 v1 = up2(acc2[mi][1]);    // h[4tn+2], h[4tn+3]
        int r = 4 * tm + mi;
        int s = (row0 & 1023) + r;

        // stash h for bias GEMM
        h_s[r * 133 + 4 * tn + 0] = v0.x;
        h_s[r * 133 + 4 * tn + 1] = v0.y;
        h_s[r * 133 + 4 * tn + 2] = v1.x;
        h_s[r * 133 + 4 * tn + 3] = v1.y;

        float fs = (float)s;
        float se, ce, so, co;
        sincosf(fs * invfe, &se, &ce);
        sincosf(fs * invfo, &so, &co);

        // RoPE: q[2tn]=h[4tn], q[2tn+1]=h[4tn+2]; k from odd h cols
        float qe = v0.x, ke = v0.y, qo = v1.x, ko = v1.y;
        qTe[s] = (qe * ce - qo * se) * 0.125f;   // fold 1/sqrt(64) into q
        qTo[s] = (qo * co + qe * so) * 0.125f;
        kTe[s] = ke * ce - ko * se;
        kTo[s] = ko * co + ke * so;
    }
    __syncthreads();                 // h_s fully written

    // bias: each thread -> row r, 4 consecutive out channels hb4..hb4+3
    {
        const int r = tid & 31;
        const int hb4 = (tid >> 5) * 4;
        float4 accb = *(const float4*)(b2 + hb4);
        const float* hp = h_s + r * 133;
#pragma unroll 8
        for (int kk = 0; kk < 128; kk++) {
            float hv = hp[kk];
            float4 wv = *(const float4*)(W2 + kk * 32 + hb4);  // uniform per warp
            accb.x += hv * wv.x;
            accb.y += hv * wv.y;
            accb.z += hv * wv.z;
            accb.w += hv * wv.w;
        }
        int s = (row0 & 1023) + r;
        float vals[4] = {accb.x * 0.5f, accb.y * 0.5f, accb.z * 0.5f, accb.w * 0.5f};
#pragma unroll
        for (int j = 0; j < 4; j++) {
            int ho = hb4 + j;
            int o = ho >> 1;
            if (ho & 1) g_bB[(size_t)(b * 16 + o) * 1024 + s] = vals[j];
            else        g_bA[(size_t)(b * 16 + o) * 1024 + s] = vals[j];
        }
    }
}

// ---------------- kernel 2: logits ----------------
// Grid: (8 n-tiles, 32 m-tiles, 4 batch), 256 threads.
// Tile: 32m x 128n; dot(q',k') computed once, reused across 16 heads.
__global__ __launch_bounds__(256) void k2_kernel(const float* __restrict__ mask,
                                                 float* __restrict__ out) {
    __shared__ __align__(16) float q_s[64 * 32];   // [k][m]
    __shared__ __align__(16) float k_s[64 * 128];  // [k][n]

    const int tid = threadIdx.x;
    const int tn = tid & 31;
    const int tm = tid >> 5;
    const int b = blockIdx.z;
    const int m0 = blockIdx.y * 32;
    const int n0 = blockIdx.x * 128;

    // stage q tile [64 d][32 m] from g_qT: coalesced float4, conflict-free STS
    {
        const float* src = g_qT + (size_t)b * 65536 + m0;
#pragma unroll
        for (int i = 0; i < 2; i++) {
            int f = tid + 256 * i;          // float4 index, 512 total
            int kk = f >> 3, col = (f & 7) * 4;
            *(float4*)&q_s[kk * 32 + col] = *(const float4*)(src + kk * 1024 + col);
        }
    }
    // stage k tile [64 d][128 n] from g_kT
    {
        const float* src = g_kT + (size_t)b * 65536 + n0;
#pragma unroll
        for (int i = 0; i < 8; i++) {
            int f = tid + 256 * i;          // float4 index, 2048 total
            int kk = f >> 5, col = (f & 31) * 4;
            *(float4*)&k_s[kk * 128 + col] = *(const float4*)(src + kk * 1024 + col);
        }
    }
    __syncthreads();

    unsigned long long acc2[4][2];
#pragma unroll
    for (int mi = 0; mi < 4; mi++) { acc2[mi][0] = 0ULL; acc2[mi][1] = 0ULL; }

#pragma unroll 16
    for (int kk = 0; kk < 64; kk++) {
        float4 av = *(const float4*)&q_s[kk * 32 + 4 * tm];  // broadcast
        ulonglong2 bv = *(const ulonglong2*)&k_s[kk * 128 + 4 * tn];
        unsigned long long am;
        am = pk2(av.x, av.x); fma2(acc2[0][0], am, bv.x); fma2(acc2[0][1], am, bv.y);
        am = pk2(av.y, av.y); fma2(acc2[1][0], am, bv.x); fma2(acc2[1][1], am, bv.y);
        am = pk2(av.z, av.z); fma2(acc2[2][0], am, bv.x); fma2(acc2[2][1], am, bv.y);
        am = pk2(av.w, av.w); fma2(acc2[3][0], am, bv.x); fma2(acc2[3][1], am, bv.y);
    }

    const int nbase = n0 + 4 * tn;
    const int mbase = m0 + 4 * tm;

    // mask terms (per n-col)
    float pm[4];
    {
        float4 mv = *(const float4*)(mask + b * 1024 + nbase);
        pm[0] = mv.x; pm[1] = mv.y; pm[2] = mv.z; pm[3] = mv.w;
    }
    unsigned long long pm2[2] = {pk2(pm[0], pm[1]), pk2(pm[2], pm[3])};

    // fold dot*pm - pen - tril*NEG into per-element constants (head-invariant)
    unsigned long long dpm2[4][2];
#pragma unroll
    for (int mi = 0; mi < 4; mi++) {
        float2 u0 = up2(acc2[mi][0]);
        float2 u1 = up2(acc2[mi][1]);
        int mg = mbase + mi;
        float c0 = -(1.0f - pm[0]) * NEGV - (mg > nbase + 0 ? NEGV : 0.0f);
        float c1 = -(1.0f - pm[1]) * NEGV - (mg > nbase + 1 ? NEGV : 0.0f);
        float c2 = -(1.0f - pm[2]) * NEGV - (mg > nbase + 2 ? NEGV : 0.0f);
        float c3 = -(1.0f - pm[3]) * NEGV - (mg > nbase + 3 ? NEGV : 0.0f);
        dpm2[mi][0] = pk2(fmaf(u0.x, pm[0], c0), fmaf(u0.y, pm[1], c1));
        dpm2[mi][1] = pk2(fmaf(u1.x, pm[2], c2), fmaf(u1.y, pm[3], c3));
    }

    float* op0 = out + ((size_t)(b * 16) * 1024 + mbase) * 1024 + nbase;
    const float* bAp = g_bA + (size_t)(b * 16) * 1024 + nbase;
    const float* bBp = g_bB + (size_t)(b * 16) * 1024 + mbase;

    for (int o = 0; o < 16; o++) {
        float4 ba = *(const float4*)(bAp + o * 1024);   // per-n bias
        float4 bb = *(const float4*)(bBp + o * 1024);   // per-m bias
        unsigned long long ba2[2] = {pk2(ba.x, ba.y), pk2(ba.z, ba.w)};
        float bbv[4] = {bb.x, bb.y, bb.z, bb.w};
        float* op = op0 + (size_t)o * 1024 * 1024;
#pragma unroll
        for (int mi = 0; mi < 4; mi++) {
            unsigned long long bb2 = pk2(bbv[mi], bbv[mi]);
            unsigned long long v0 = fma2n(add2(ba2[0], bb2), pm2[0], dpm2[mi][0]);
            unsigned long long v1 = fma2n(add2(ba2[1], bb2), pm2[1], dpm2[mi][1]);
            float2 r0 = up2(v0);
            float2 r1 = up2(v1);
            float4 r = make_float4(r0.x, r0.y, r1.x, r1.y);
            __stcs((float4*)(op + (size_t)mi * 1024), r);
        }
    }
}

extern "C" void kernel_launch(void* const* d_in, const int* in_sizes, int n_in,
                              void* d_out, int out_size) {
    const float* x    = (const float*)d_in[0];  // (4,1024,768)
    const float* mask = (const float*)d_in[1];  // (4,1024)
    const float* W1   = (const float*)d_in[2];  // (768,128)
    const float* b1   = (const float*)d_in[3];  // (128)
    const float* W2   = (const float*)d_in[4];  // (128,32)
    const float* b2   = (const float*)d_in[5];  // (32)
    float* out = (float*)d_out;                 // (4,16,1024,1024)

    k1_kernel<<<128, 256>>>(x, W1, b1, W2, b2);
    k2_kernel<<<dim3(8, 32, 4), 256>>>(mask, out);
}

// round 4
// speedup vs baseline: 1.1908x; 1.0260x over previous
#include <cuda_runtime.h>
#include <cstdint>
#include <math.h>

#define NEGV 1000000000000.0f

// ---------------- scratch (static device globals; no allocs) ----------------
__device__ float g_hp[2 * 4096 * 128];   // K-split partial h
__device__ float g_qT[4 * 64 * 1024];    // rope'd q, TRANSPOSED [b][d][m], pre-scaled 1/8
__device__ float g_kT[4 * 64 * 1024];    // rope'd k, TRANSPOSED [b][d][n]
__device__ float g_bA[4 * 16 * 1024];    // bias[b, n, 2o]/2   -> indexed [b][o][n]
__device__ float g_bB[4 * 16 * 1024];    // bias[b, m, 2o+1]/2 -> indexed [b][o][m]

// ---------------- packed f32x2 helpers ----------------
__device__ __forceinline__ unsigned long long pk2(float lo, float hi) {
    unsigned long long r;
    asm("mov.b64 %0, {%1,%2};" : "=l"(r) : "f"(lo), "f"(hi));
    return r;
}
__device__ __forceinline__ void fma2(unsigned long long& d, unsigned long long a,
                                     unsigned long long b) {
    asm("fma.rn.f32x2 %0, %1, %2, %0;" : "+l"(d) : "l"(a), "l"(b));
}
__device__ __forceinline__ unsigned long long fma2n(unsigned long long a,
                                                    unsigned long long b,
                                                    unsigned long long c) {
    unsigned long long d;
    asm("fma.rn.f32x2 %0, %1, %2, %3;" : "=l"(d) : "l"(a), "l"(b), "l"(c));
    return d;
}
__device__ __forceinline__ unsigned long long add2(unsigned long long a,
                                                   unsigned long long b) {
    unsigned long long d;
    asm("add.rn.f32x2 %0, %1, %2;" : "=l"(d) : "l"(a), "l"(b));
    return d;
}
__device__ __forceinline__ float2 up2(unsigned long long v) {
    float2 r;
    asm("mov.b64 {%0,%1}, %2;" : "=f"(r.x), "=f"(r.y) : "l"(v));
    return r;
}

// ---------------- kernel 1a: partial GEMM h_partial = x@W1 (K-split) --------
// Grid: dim3(2, 64) -> blockIdx.x = k-split, blockIdx.y = m-block (64 rows).
// 128 threads, BM=64, BN=128, BK-tile=64, 6 tiles per split.
// Micro-tile 8m x 8n: 64B LDS per 64 FMA -> crossbar matches fma floor.
__global__ __launch_bounds__(128) void k1a_kernel(
    const float* __restrict__ x, const float* __restrict__ W1) {
    __shared__ __align__(16) float a_s[64 * 64];   // [k][m], no pad needed
    __shared__ __align__(16) float b_s[64 * 128];  // [k][n]

    const int tid = threadIdx.x;
    const int ks = blockIdx.x;          // 0/1 k-split
    const int row0 = blockIdx.y * 64;
    const int kbase = ks * 384;

    const int tn = tid & 15;            // 8 n-cols: 8*tn .. 8*tn+7
    const int tm = tid >> 4;            // 8 m-rows: 8*tm .. 8*tm+7

    // A staging: row per lane-pair, thread owns 32 consecutive k as 8 float4
    const int ar = tid & 63;
    const int khalf = (tid >> 6) * 32;

    unsigned long long acc2[8][4];
#pragma unroll
    for (int mi = 0; mi < 8; mi++)
#pragma unroll
        for (int nj = 0; nj < 4; nj++) acc2[mi][nj] = 0ULL;

    float4 pa[8], pb[16];
    // prefetch tile 0
    {
        const float* xp = x + (size_t)(row0 + ar) * 768 + kbase + khalf;
#pragma unroll
        for (int j = 0; j < 8; j++) pa[j] = *(const float4*)(xp + 4 * j);
#pragma unroll
        for (int i = 0; i < 16; i++) {
            int f = tid + 128 * i;
            int kk = f >> 5, col = (f & 31) * 4;
            pb[i] = *(const float4*)(W1 + (size_t)(kbase + kk) * 128 + col);
        }
    }

    for (int kt = 0; kt < 6; kt++) {
        __syncthreads();
        // stage A transposed: a_s[k][m]
#pragma unroll
        for (int j = 0; j < 8; j++) {
            int kb = khalf + 4 * j;
            a_s[(kb + 0) * 64 + ar] = pa[j].x;
            a_s[(kb + 1) * 64 + ar] = pa[j].y;
            a_s[(kb + 2) * 64 + ar] = pa[j].z;
            a_s[(kb + 3) * 64 + ar] = pa[j].w;
        }
        // stage B: b_s[k][n]
#pragma unroll
        for (int i = 0; i < 16; i++) {
            int f = tid + 128 * i;
            int kk = f >> 5, col = (f & 31) * 4;
            *(float4*)&b_s[kk * 128 + col] = pb[i];
        }
        __syncthreads();

        // prefetch next tile
        if (kt < 5) {
            int k0n = kbase + (kt + 1) * 64;
            const float* xp = x + (size_t)(row0 + ar) * 768 + k0n + khalf;
#pragma unroll
            for (int j = 0; j < 8; j++) pa[j] = *(const float4*)(xp + 4 * j);
#pragma unroll
            for (int i = 0; i < 16; i++) {
                int f = tid + 128 * i;
                int kk = f >> 5, col = (f & 31) * 4;
                pb[i] = *(const float4*)(W1 + (size_t)(k0n + kk) * 128 + col);
            }
        }

#pragma unroll 8
        for (int kk = 0; kk < 64; kk++) {
            float4 a0 = *(const float4*)&a_s[kk * 64 + 8 * tm];
            float4 a1 = *(const float4*)&a_s[kk * 64 + 8 * tm + 4];
            ulonglong2 bv0 = *(const ulonglong2*)&b_s[kk * 128 + 8 * tn];
            ulonglong2 bv1 = *(const ulonglong2*)&b_s[kk * 128 + 8 * tn + 4];
            unsigned long long am;
            am = pk2(a0.x, a0.x);
            fma2(acc2[0][0], am, bv0.x); fma2(acc2[0][1], am, bv0.y);
            fma2(acc2[0][2], am, bv1.x); fma2(acc2[0][3], am, bv1.y);
            am = pk2(a0.y, a0.y);
            fma2(acc2[1][0], am, bv0.x); fma2(acc2[1][1], am, bv0.y);
            fma2(acc2[1][2], am, bv1.x); fma2(acc2[1][3], am, bv1.y);
            am = pk2(a0.z, a0.z);
            fma2(acc2[2][0], am, bv0.x); fma2(acc2[2][1], am, bv0.y);
            fma2(acc2[2][2], am, bv1.x); fma2(acc2[2][3], am, bv1.y);
            am = pk2(a0.w, a0.w);
            fma2(acc2[3][0], am, bv0.x); fma2(acc2[3][1], am, bv0.y);
            fma2(acc2[3][2], am, bv1.x); fma2(acc2[3][3], am, bv1.y);
            am = pk2(a1.x, a1.x);
            fma2(acc2[4][0], am, bv0.x); fma2(acc2[4][1], am, bv0.y);
            fma2(acc2[4][2], am, bv1.x); fma2(acc2[4][3], am, bv1.y);
            am = pk2(a1.y, a1.y);
            fma2(acc2[5][0], am, bv0.x); fma2(acc2[5][1], am, bv0.y);
            fma2(acc2[5][2], am, bv1.x); fma2(acc2[5][3], am, bv1.y);
            am = pk2(a1.z, a1.z);
            fma2(acc2[6][0], am, bv0.x); fma2(acc2[6][1], am, bv0.y);
            fma2(acc2[6][2], am, bv1.x); fma2(acc2[6][3], am, bv1.y);
            am = pk2(a1.w, a1.w);
            fma2(acc2[7][0], am, bv0.x); fma2(acc2[7][1], am, bv0.y);
            fma2(acc2[7][2], am, bv1.x); fma2(acc2[7][3], am, bv1.y);
        }
    }

    // write partial h
    float* hp = g_hp + (size_t)ks * 4096 * 128;
#pragma unroll
    for (int mi = 0; mi < 8; mi++) {
        float2 p0 = up2(acc2[mi][0]);
        float2 p1 = up2(acc2[mi][1]);
        float2 p2 = up2(acc2[mi][2]);
        float2 p3 = up2(acc2[mi][3]);
        size_t off = (size_t)(row0 + 8 * tm + mi) * 128 + 8 * tn;
        *(float4*)(hp + off)     = make_float4(p0.x, p0.y, p1.x, p1.y);
        *(float4*)(hp + off + 4) = make_float4(p2.x, p2.y, p3.x, p3.y);
    }
}

// ---------------- kernel 1b: combine + RoPE -> qT/kT, bias -> bA/bB ---------
// Grid: 128 blocks (32 rows each), 256 threads.
__global__ __launch_bounds__(256) void k1b_kernel(
    const float* __restrict__ b1, const float* __restrict__ W2,
    const float* __restrict__ b2) {
    __shared__ float h_s[32 * 133];
    __shared__ float invf_s[32];

    const int tid = threadIdx.x;
    const int tn = tid & 31;   // cols 4*tn .. 4*tn+3
    const int tm = tid >> 5;   // rows 4*tm .. 4*tm+3
    const int row0 = blockIdx.x * 32;
    const int b = row0 >> 10;

    if (tid < 32) {
        invf_s[tid] = (float)exp(-(double)tid * (9.210340371976184 / 32.0));
    }
    __syncthreads();

    const int ie = (2 * tn) & 31;
    const int io = (2 * tn + 1) & 31;
    const float invfe = invf_s[ie];
    const float invfo = invf_s[io];
    float* qTe = g_qT + (size_t)(b * 64 + 2 * tn) * 1024;
    float* qTo = qTe + 1024;
    float* kTe = g_kT + (size_t)(b * 64 + 2 * tn) * 1024;
    float* kTo = kTe + 1024;

    float4 b1v = *(const float4*)(b1 + 4 * tn);

#pragma unroll
    for (int mi = 0; mi < 4; mi++) {
        int r = 4 * tm + mi;
        int rg = row0 + r;
        int s = rg & 1023;
        float4 u = *(const float4*)(g_hp + (size_t)rg * 128 + 4 * tn);
        float4 w = *(const float4*)(g_hp + (size_t)(4096 * 128) + (size_t)rg * 128 + 4 * tn);
        float h0 = u.x + w.x + b1v.x;
        float h1 = u.y + w.y + b1v.y;
        float h2 = u.z + w.z + b1v.z;
        float h3 = u.w + w.w + b1v.w;

        // stash h for bias GEMM
        h_s[r * 133 + 4 * tn + 0] = h0;
        h_s[r * 133 + 4 * tn + 1] = h1;
        h_s[r * 133 + 4 * tn + 2] = h2;
        h_s[r * 133 + 4 * tn + 3] = h3;

        float fs = (float)s;
        float se, ce, so, co;
        sincosf(fs * invfe, &se, &ce);
        sincosf(fs * invfo, &so, &co);

        // RoPE: q from even h cols (h0,h2), k from odd (h1,h3)
        qTe[s] = (h0 * ce - h2 * se) * 0.125f;   // fold 1/sqrt(64) into q
        qTo[s] = (h2 * co + h0 * so) * 0.125f;
        kTe[s] = h1 * ce - h3 * se;
        kTo[s] = h3 * co + h1 * so;
    }
    __syncthreads();   // h_s fully written

    // bias: each thread -> row r, 4 consecutive out channels hb4..hb4+3
    {
        const int r = tid & 31;
        const int hb4 = (tid >> 5) * 4;
        float4 accb = *(const float4*)(b2 + hb4);
        const float* hp = h_s + r * 133;
#pragma unroll 8
        for (int kk = 0; kk < 128; kk++) {
            float hv = hp[kk];
            float4 wv = *(const float4*)(W2 + kk * 32 + hb4);  // uniform per warp
            accb.x += hv * wv.x;
            accb.y += hv * wv.y;
            accb.z += hv * wv.z;
            accb.w += hv * wv.w;
        }
        int s = (row0 & 1023) + r;
        float vals[4] = {accb.x * 0.5f, accb.y * 0.5f, accb.z * 0.5f, accb.w * 0.5f};
#pragma unroll
        for (int j = 0; j < 4; j++) {
            int ho = hb4 + j;
            int o = ho >> 1;
            if (ho & 1) g_bB[(size_t)(b * 16 + o) * 1024 + s] = vals[j];
            else        g_bA[(size_t)(b * 16 + o) * 1024 + s] = vals[j];
        }
    }
}

// ---------------- kernel 2: logits (unchanged from R2) ----------------
__global__ __launch_bounds__(256) void k2_kernel(const float* __restrict__ mask,
                                                 float* __restrict__ out) {
    __shared__ __align__(16) float q_s[64 * 32];   // [k][m]
    __shared__ __align__(16) float k_s[64 * 128];  // [k][n]

    const int tid = threadIdx.x;
    const int tn = tid & 31;
    const int tm = tid >> 5;
    const int b = blockIdx.z;
    const int m0 = blockIdx.y * 32;
    const int n0 = blockIdx.x * 128;

    // stage q tile [64 d][32 m] from g_qT: coalesced float4, conflict-free STS
    {
        const float* src = g_qT + (size_t)b * 65536 + m0;
#pragma unroll
        for (int i = 0; i < 2; i++) {
            int f = tid + 256 * i;
            int kk = f >> 3, col = (f & 7) * 4;
            *(float4*)&q_s[kk * 32 + col] = *(const float4*)(src + kk * 1024 + col);
        }
    }
    // stage k tile [64 d][128 n] from g_kT
    {
        const float* src = g_kT + (size_t)b * 65536 + n0;
#pragma unroll
        for (int i = 0; i < 8; i++) {
            int f = tid + 256 * i;
            int kk = f >> 5, col = (f & 31) * 4;
            *(float4*)&k_s[kk * 128 + col] = *(const float4*)(src + kk * 1024 + col);
        }
    }
    __syncthreads();

    unsigned long long acc2[4][2];
#pragma unroll
    for (int mi = 0; mi < 4; mi++) { acc2[mi][0] = 0ULL; acc2[mi][1] = 0ULL; }

#pragma unroll 16
    for (int kk = 0; kk < 64; kk++) {
        float4 av = *(const float4*)&q_s[kk * 32 + 4 * tm];  // broadcast
        ulonglong2 bv = *(const ulonglong2*)&k_s[kk * 128 + 4 * tn];
        unsigned long long am;
        am = pk2(av.x, av.x); fma2(acc2[0][0], am, bv.x); fma2(acc2[0][1], am, bv.y);
        am = pk2(av.y, av.y); fma2(acc2[1][0], am, bv.x); fma2(acc2[1][1], am, bv.y);
        am = pk2(av.z, av.z); fma2(acc2[2][0], am, bv.x); fma2(acc2[2][1], am, bv.y);
        am = pk2(av.w, av.w); fma2(acc2[3][0], am, bv.x); fma2(acc2[3][1], am, bv.y);
    }

    const int nbase = n0 + 4 * tn;
    const int mbase = m0 + 4 * tm;

    // mask terms (per n-col)
    float pm[4];
    {
        float4 mv = *(const float4*)(mask + b * 1024 + nbase);
        pm[0] = mv.x; pm[1] = mv.y; pm[2] = mv.z; pm[3] = mv.w;
    }
    unsigned long long pm2[2] = {pk2(pm[0], pm[1]), pk2(pm[2], pm[3])};

    // fold dot*pm - pen - tril*NEG into per-element constants (head-invariant)
    unsigned long long dpm2[4][2];
#pragma unroll
    for (int mi = 0; mi < 4; mi++) {
        float2 u0 = up2(acc2[mi][0]);
        float2 u1 = up2(acc2[mi][1]);
        int mg = mbase + mi;
        float c0 = -(1.0f - pm[0]) * NEGV - (mg > nbase + 0 ? NEGV : 0.0f);
        float c1 = -(1.0f - pm[1]) * NEGV - (mg > nbase + 1 ? NEGV : 0.0f);
        float c2 = -(1.0f - pm[2]) * NEGV - (mg > nbase + 2 ? NEGV : 0.0f);
        float c3 = -(1.0f - pm[3]) * NEGV - (mg > nbase + 3 ? NEGV : 0.0f);
        dpm2[mi][0] = pk2(fmaf(u0.x, pm[0], c0), fmaf(u0.y, pm[1], c1));
        dpm2[mi][1] = pk2(fmaf(u1.x, pm[2], c2), fmaf(u1.y, pm[3], c3));
    }

    float* op0 = out + ((size_t)(b * 16) * 1024 + mbase) * 1024 + nbase;
    const float* bAp = g_bA + (size_t)(b * 16) * 1024 + nbase;
    const float* bBp = g_bB + (size_t)(b * 16) * 1024 + mbase;

    for (int o = 0; o < 16; o++) {
        float4 ba = *(const float4*)(bAp + o * 1024);   // per-n bias
        float4 bb = *(const float4*)(bBp + o * 1024);   // per-m bias
        unsigned long long ba2[2] = {pk2(ba.x, ba.y), pk2(ba.z, ba.w)};
        float bbv[4] = {bb.x, bb.y, bb.z, bb.w};
        float* op = op0 + (size_t)o * 1024 * 1024;
#pragma unroll
        for (int mi = 0; mi < 4; mi++) {
            unsigned long long bb2 = pk2(bbv[mi], bbv[mi]);
            unsigned long long v0 = fma2n(add2(ba2[0], bb2), pm2[0], dpm2[mi][0]);
            unsigned long long v1 = fma2n(add2(ba2[1], bb2), pm2[1], dpm2[mi][1]);
            float2 r0 = up2(v0);
            float2 r1 = up2(v1);
            float4 r = make_float4(r0.x, r0.y, r1.x, r1.y);
            __stcs((float4*)(op + (size_t)mi * 1024), r);
        }
    }
}

extern "C" void kernel_launch(void* const* d_in, const int* in_sizes, int n_in,
                              void* d_out, int out_size) {
    const float* x    = (const float*)d_in[0];  // (4,1024,768)
    const float* mask = (const float*)d_in[1];  // (4,1024)
    const float* W1   = (const float*)d_in[2];  // (768,128)
    const float* b1   = (const float*)d_in[3];  // (128)
    const float* W2   = (const float*)d_in[4];  // (128,32)
    const float* b2   = (const float*)d_in[5];  // (32)
    float* out = (float*)d_out;                 // (4,16,1024,1024)

    k1a_kernel<<<dim3(2, 64), 128>>>(x, W1);
    k1b_kernel<<<128, 256>>>(b1, W2, b2);
    k2_kernel<<<dim3(8, 32, 4), 256>>>(mask, out);
}